// round 6
// baseline (speedup 1.0000x reference)
#include <cuda_runtime.h>
#include <cuda_fp16.h>
#include <cstdint>

// Problem constants
#define VOCAB 32000
#define EMB   64
#define HID   64
#define BATCH 16
#define SEQ   256
#define ROWS  (BATCH*SEQ)   // 4096
#define G3    (3*HID)       // 192
#define NCHUNK 16           // 16 chunks of 16 steps
#define GRU_BLOCKS 16
#define WCONV_BLOCKS 2000   // 512000 float4 / 256

// Scratch (device globals; no allocation allowed)
__device__ float  g_xp[ROWS * G3];          // x @ w_ih^T + b_ih
__device__ __half g_hh[ROWS * HID];         // h, layout [chunk][batch][s%16][64]
__device__ __half g_wh[VOCAB * HID];        // w_out fp16
__device__ int    g_cnt[NCHUNK];            // chunk completion counters

// ---------------------------------------------------------------------------
// helpers
// ---------------------------------------------------------------------------
__device__ __forceinline__ void fma2(unsigned long long& d,
                                     unsigned long long a, unsigned long long b) {
    asm("fma.rn.f32x2 %0, %1, %2, %0;" : "+l"(d) : "l"(a), "l"(b));
}
__device__ __forceinline__ float upsum(unsigned long long v) {
    unsigned lo, hi;
    asm("mov.b64 {%0,%1}, %2;" : "=r"(lo), "=r"(hi) : "l"(v));
    return __uint_as_float(lo) + __uint_as_float(hi);
}
__device__ __forceinline__ float frcp(float x) {
    float r; asm("rcp.approx.f32 %0, %1;" : "=f"(r) : "f"(x)); return r;
}
__device__ __forceinline__ float fsigm(float x) { return frcp(1.f + __expf(-x)); }
__device__ __forceinline__ float ftanh(float x) {
    return 1.f - 2.f * frcp(__expf(2.f * x) + 1.f);
}
__device__ __forceinline__ void ldsm_x4(uint32_t* r, uint32_t addr) {
    asm volatile("ldmatrix.sync.aligned.m8n8.x4.shared.b16 {%0,%1,%2,%3}, [%4];"
                 : "=r"(r[0]), "=r"(r[1]), "=r"(r[2]), "=r"(r[3]) : "r"(addr));
}
__device__ __forceinline__ void mma16816(float* d, const uint32_t* a, const uint32_t* b) {
    asm volatile(
        "mma.sync.aligned.m16n8k16.row.col.f32.f16.f16.f32 "
        "{%0,%1,%2,%3},{%4,%5,%6,%7},{%8,%9},{%0,%1,%2,%3};"
        : "+f"(d[0]), "+f"(d[1]), "+f"(d[2]), "+f"(d[3])
        : "r"(a[0]), "r"(a[1]), "r"(a[2]), "r"(a[3]), "r"(b[0]), "r"(b[1]));
}
__device__ __forceinline__ uint32_t smem_u32(const void* p) {
    uint32_t a;
    asm("{ .reg .u64 t; cvta.to.shared.u64 t, %1; cvt.u32.u64 %0, t; }"
        : "=r"(a) : "l"(p));
    return a;
}
// g_hh row R -> original (b,s) C row:  b = (R>>4)&15, s = (R>>8)*16 + (R&15)
__device__ __forceinline__ int crow(int R) {
    return (((R >> 4) & 15) << 8) + ((R >> 8) << 4) + (R & 15);
}

// ---------------------------------------------------------------------------
// Prep kernel: blocks [0,2000) convert w_out fp32->fp16;
// blocks [2000, 2128) do embedding + input projection (+ flag reset).
// ---------------------------------------------------------------------------
__global__ __launch_bounds__(256) void prep_kernel(
    const float* __restrict__ W,
    const int* __restrict__ tokens, const float* __restrict__ emb,
    const float* __restrict__ w_ih, const float* __restrict__ b_ih)
{
    const int tid = threadIdx.x;

    if (blockIdx.x < WCONV_BLOCKS) {
        size_t i = (size_t)blockIdx.x * 256 + tid;
        float4 v = reinterpret_cast<const float4*>(W)[i];
        __half2* d = reinterpret_cast<__half2*>(g_wh + i * 4);
        d[0] = __floats2half2_rn(v.x, v.y);
        d[1] = __floats2half2_rn(v.z, v.w);
        return;
    }

    __shared__ __align__(16) float xs[32][EMB];
    __shared__ int toks[32];

    const int g = tid;
    const int rowbase = (blockIdx.x - WCONV_BLOCKS) * 32;

    if (blockIdx.x == WCONV_BLOCKS && g < NCHUNK) g_cnt[g] = 0;
    if (g < 32) toks[g] = tokens[rowbase + g];

    float4 w4[16];
    float bi = 0.f;
    if (g < G3) {
        const float4* wr = reinterpret_cast<const float4*>(w_ih + g * EMB);
#pragma unroll
        for (int i = 0; i < 16; ++i) w4[i] = wr[i];
        bi = b_ih[g];
    }
    __syncthreads();
    for (int idx = g; idx < 32 * EMB; idx += 256) {
        int r = idx >> 6, c = idx & 63;
        xs[r][c] = emb[(int64_t)toks[r] * EMB + c];
    }
    __syncthreads();

    if (g < G3) {
#pragma unroll 4
        for (int r = 0; r < 32; ++r) {
            const float4* xv = reinterpret_cast<const float4*>(xs[r]);
            float a0 = bi, a1 = 0.f, a2 = 0.f, a3 = 0.f;
#pragma unroll
            for (int i = 0; i < 16; ++i) {
                float4 h4 = xv[i];
                a0 += w4[i].x * h4.x;
                a1 += w4[i].y * h4.y;
                a2 += w4[i].z * h4.z;
                a3 += w4[i].w * h4.w;
            }
            g_xp[(rowbase + r) * G3 + g] = (a0 + a1) + (a2 + a3);
        }
    }
}

// ---------------------------------------------------------------------------
// Fat kernel: blocks 0..15 = GRU (one batch each, 256 threads, 4 per h-idx);
// blocks 16.. = GEMM tiles gated on chunk flags.
// ---------------------------------------------------------------------------
#define GM 128
#define GN 128
#define LDS_H 72          // halves per smem A/B row (64 + 8 pad)
#define XBUF_F 3072       // floats per xp chunk (16 steps * 192)

__global__ __launch_bounds__(256, 2) void fat_kernel(
    const float* __restrict__ w_hh, const float* __restrict__ b_hh,
    const float* __restrict__ bias, float* __restrict__ C)
{
    __shared__ __align__(16) char smraw[GM * LDS_H * 2 + GN * LDS_H * 2]; // 36864

    const int tid = threadIdx.x;

    if (blockIdx.x < GRU_BLOCKS) {
        // ================= GRU role =================
        float* xbuf = reinterpret_cast<float*>(smraw);              // [2][3072]
        float* hsm  = reinterpret_cast<float*>(smraw + 2 * XBUF_F * 4); // [2][64]

        const int t  = tid;
        const int p  = t >> 2;        // h index 0..63
        const int q  = t & 3;         // k quarter
        const int k0 = q * 16;
        const int b  = blockIdx.x;
        const int row0 = b * SEQ;

        // weights: rows p, p+64, p+128, k-slice [k0,k0+16) = 8 u64 per gate
        unsigned long long wr[8], wz[8], wn[8];
        {
            const unsigned long long* Wr =
                reinterpret_cast<const unsigned long long*>(w_hh + (p      ) * HID + k0);
            const unsigned long long* Wz =
                reinterpret_cast<const unsigned long long*>(w_hh + (p +  64) * HID + k0);
            const unsigned long long* Wn =
                reinterpret_cast<const unsigned long long*>(w_hh + (p + 128) * HID + k0);
#pragma unroll
            for (int i = 0; i < 8; ++i) { wr[i] = Wr[i]; wz[i] = Wz[i]; wn[i] = Wn[i]; }
        }
        const float br = b_hh[p], bz = b_hh[p + 64], bn = b_hh[p + 128];

        if (t < 2 * HID) hsm[t] = 0.f;

        // stage chunk 0 into xbuf[0]; prefetch chunk 1 into regs
        const float4* src = reinterpret_cast<const float4*>(g_xp + (size_t)row0 * G3);
        {
            float4 a = src[t], c = src[t + 256], d = src[t + 512];
            float4* dst = reinterpret_cast<float4*>(xbuf);
            dst[t] = a; dst[t + 256] = c; dst[t + 512] = d;
        }
        float4 pf0 = src[t + 768], pf1 = src[t + 1024], pf2 = src[t + 1280];
        float h_old = 0.f;
        __syncthreads();

        int cb = 0, cur = 0;
#pragma unroll 1
        for (int s = 0; s < SEQ; ++s) {
            const int sl = s & 15;

            // issue LDG prefetch for chunk (s>>4)+1 at each chunk start
            if (sl == 0 && s > 0 && ((s >> 4) + 1) < NCHUNK) {
                const float4* srcn = src + (size_t)((s >> 4) + 1) * 768;
                pf0 = srcn[t]; pf1 = srcn[t + 256]; pf2 = srcn[t + 512];
            }

            const float* xrow = xbuf + cb * XBUF_F + sl * G3;
            const float xr = xrow[p], xz = xrow[p + 64], xn = xrow[p + 128];

            // partial matvec over 16-wide k-quarter (packed f32x2)
            unsigned long long ar0 = 0, ar1 = 0, az0 = 0, az1 = 0, an0 = 0, an1 = 0;
            const unsigned long long* h2 =
                reinterpret_cast<const unsigned long long*>(hsm + cur * HID + k0);
#pragma unroll
            for (int i = 0; i < 8; i += 2) {
                unsigned long long h0 = h2[i], h1 = h2[i + 1];
                fma2(ar0, wr[i], h0); fma2(ar1, wr[i + 1], h1);
                fma2(az0, wz[i], h0); fma2(az1, wz[i + 1], h1);
                fma2(an0, wn[i], h0); fma2(an1, wn[i + 1], h1);
            }
            float dr = upsum(ar0) + upsum(ar1);
            float dz = upsum(az0) + upsum(az1);
            float dn = upsum(an0) + upsum(an1);
            dr += __shfl_xor_sync(0xffffffffu, dr, 1);
            dz += __shfl_xor_sync(0xffffffffu, dz, 1);
            dn += __shfl_xor_sync(0xffffffffu, dn, 1);
            dr += __shfl_xor_sync(0xffffffffu, dr, 2);
            dz += __shfl_xor_sync(0xffffffffu, dz, 2);
            dn += __shfl_xor_sync(0xffffffffu, dn, 2);

            const float r = fsigm(xr + br + dr);
            const float z = fsigm(xz + bz + dz);
            const float n = ftanh(xn + r * (dn + bn));
            const float hnew = n + z * (h_old - n);

            if (q == 0) {
                hsm[(cur ^ 1) * HID + p] = hnew;
                const int hrow = ((s >> 4) * 16 + b) * 16 + sl;  // [chunk][b][s%16]
                g_hh[(size_t)hrow * HID + p] = __float2half_rn(hnew);
            }
            h_old = hnew;

            // at chunk end: commit prefetched next chunk to the other buffer
            if (sl == 15 && ((s >> 4) + 1) < NCHUNK) {
                float4* dst = reinterpret_cast<float4*>(xbuf + (cb ^ 1) * XBUF_F);
                dst[t] = pf0; dst[t + 256] = pf1; dst[t + 512] = pf2;
            }
            __syncthreads();
            if (sl == 15) {
                if (t == 0) {
                    __threadfence();
                    atomicAdd(&g_cnt[s >> 4], 1);
                }
                cb ^= 1;
            }
            cur ^= 1;
        }
        return;
    }

    // ================= GEMM role =================
    __half* As = reinterpret_cast<__half*>(smraw);
    __half* Bs = As + GM * LDS_H;

    const int gid   = blockIdx.x - GRU_BLOCKS;
    const int bx    = gid % (VOCAB / GN);     // 0..249
    const int by    = gid / (VOCAB / GN);     // 0..31
    const int chunk = by >> 1;
    const int nbase = bx * GN;

    // wait for chunk (all 16 GRU blocks past step 16*chunk+15)
    {
        volatile int* cp = &g_cnt[chunk];
        while (*cp < BATCH) __nanosleep(1000);
        __threadfence();
    }

    const int wid   = tid >> 5;
    const int lane  = tid & 31;
    const int wm    = wid >> 2;     // 0..1
    const int wn    = wid & 3;      // 0..3

    // ---- stage A (g_hh rows by*128..+127) and B (g_wh rows nbase..+127) ----
    {
        const uint4* Ag = reinterpret_cast<const uint4*>(g_hh + (size_t)by * GM * HID);
        const uint4* Bg = reinterpret_cast<const uint4*>(g_wh + (size_t)nbase * HID);
#pragma unroll
        for (int i = 0; i < 4; ++i) {
            int idx = tid + i * 256;
            int m = idx >> 3, c = idx & 7;
            *reinterpret_cast<uint4*>(As + m * LDS_H + c * 8) = Ag[idx];
            *reinterpret_cast<uint4*>(Bs + m * LDS_H + c * 8) = Bg[idx];
        }
    }
    __syncthreads();

    const uint32_t As_u = smem_u32(As);
    const uint32_t Bs_u = smem_u32(Bs);

    const int a_row = wm * 64 + ((lane >> 3) & 1) * 8 + (lane & 7);
    const int a_kc  = (lane >> 4) * 16;
    const int b_row = wn * 32 + (lane >> 4) * 8 + (lane & 7);
    const int b_kc  = ((lane >> 3) & 1) * 16;

    float acc[4][4][4];
#pragma unroll
    for (int mt = 0; mt < 4; ++mt)
#pragma unroll
        for (int nt = 0; nt < 4; ++nt)
#pragma unroll
            for (int r = 0; r < 4; ++r) acc[mt][nt][r] = 0.f;

#pragma unroll
    for (int ks = 0; ks < 4; ++ks) {
        uint32_t a[4][4], bfr[2][4];
#pragma unroll
        for (int mt = 0; mt < 4; ++mt)
            ldsm_x4(a[mt], As_u + (uint32_t)((a_row + mt * 16) * 144 + ks * 32 + a_kc));
#pragma unroll
        for (int p = 0; p < 2; ++p)
            ldsm_x4(bfr[p], Bs_u + (uint32_t)((b_row + p * 16) * 144 + ks * 32 + b_kc));
#pragma unroll
        for (int mt = 0; mt < 4; ++mt)
#pragma unroll
            for (int nt = 0; nt < 4; ++nt)
                mma16816(acc[mt][nt], a[mt], &bfr[nt >> 1][(nt & 1) * 2]);
    }

    // ---- epilogue: bias add + direct float2 stores (row-permuted C) ----
    const int col_l = nbase + wn * 32 + 2 * (lane & 3);
    float2 bv[4];
#pragma unroll
    for (int nt = 0; nt < 4; ++nt)
        bv[nt] = *reinterpret_cast<const float2*>(bias + col_l + nt * 8);

    const int Rbase = by * GM + wm * 64 + (lane >> 2);
#pragma unroll
    for (int mt = 0; mt < 4; ++mt) {
        const size_t r0 = (size_t)crow(Rbase + mt * 16)     * VOCAB;
        const size_t r1 = (size_t)crow(Rbase + mt * 16 + 8) * VOCAB;
#pragma unroll
        for (int nt = 0; nt < 4; ++nt) {
            float2 v0 = make_float2(acc[mt][nt][0] + bv[nt].x, acc[mt][nt][1] + bv[nt].y);
            float2 v1 = make_float2(acc[mt][nt][2] + bv[nt].x, acc[mt][nt][3] + bv[nt].y);
            *reinterpret_cast<float2*>(C + r0 + col_l + nt * 8) = v0;
            *reinterpret_cast<float2*>(C + r1 + col_l + nt * 8) = v1;
        }
    }
}

// ---------------------------------------------------------------------------
// Launch
// Inputs: 0 tokens(int32) 1 emb 2 w_ih 3 w_hh 4 b_ih 5 b_hh 6 w_out 7 b_out
// ---------------------------------------------------------------------------
extern "C" void kernel_launch(void* const* d_in, const int* in_sizes, int n_in,
                              void* d_out, int out_size)
{
    const int*   tokens = (const int*)  d_in[0];
    const float* emb    = (const float*)d_in[1];
    const float* w_ih   = (const float*)d_in[2];
    const float* w_hh   = (const float*)d_in[3];
    const float* b_ih   = (const float*)d_in[4];
    const float* b_hh   = (const float*)d_in[5];
    const float* w_out  = (const float*)d_in[6];
    const float* b_out  = (const float*)d_in[7];
    float* out = (float*)d_out;

    (void)in_sizes; (void)n_in; (void)out_size;

    prep_kernel<<<WCONV_BLOCKS + ROWS / 32, 256>>>(w_out, tokens, emb, w_ih, b_ih);

    const int gemm_blocks = (VOCAB / GN) * (ROWS / GM);   // 250*32 = 8000
    fat_kernel<<<GRU_BLOCKS + gemm_blocks, 256>>>(w_hh, b_hh, b_out, out);
}

// round 7
// speedup vs baseline: 1.3404x; 1.3404x over previous
#include <cuda_runtime.h>
#include <cuda_fp16.h>
#include <cstdint>

// Problem constants
#define VOCAB 32000
#define EMB   64
#define HID   64
#define BATCH 16
#define SEQ   256
#define ROWS  (BATCH*SEQ)   // 4096
#define G3    (3*HID)       // 192
#define NCHUNK 16           // 16 chunks of 16 steps
#define GRU_BLOCKS 16
#define NGEMM 132           // persistent GEMM blocks
#define GRID_FAT (GRU_BLOCKS + NGEMM)   // 148 = one block per SM
#define WCONV_BLOCKS 2000   // 512000 float4 / 256

// Scratch (device globals; no allocation allowed)
__device__ float  g_xp[ROWS * G3];          // x @ w_ih^T + b_ih
__device__ __half g_hh[ROWS * HID];         // h, layout [chunk][batch][s%16][64]
__device__ __half g_wh[VOCAB * HID];        // w_out fp16
__device__ int    g_cnt[NCHUNK];            // chunk completion counters

// ---------------------------------------------------------------------------
// helpers
// ---------------------------------------------------------------------------
__device__ __forceinline__ void fma2(unsigned long long& d,
                                     unsigned long long a, unsigned long long b) {
    asm("fma.rn.f32x2 %0, %1, %2, %0;" : "+l"(d) : "l"(a), "l"(b));
}
__device__ __forceinline__ float upsum(unsigned long long v) {
    unsigned lo, hi;
    asm("mov.b64 {%0,%1}, %2;" : "=r"(lo), "=r"(hi) : "l"(v));
    return __uint_as_float(lo) + __uint_as_float(hi);
}
__device__ __forceinline__ float frcp(float x) {
    float r; asm("rcp.approx.f32 %0, %1;" : "=f"(r) : "f"(x)); return r;
}
__device__ __forceinline__ float fsigm(float x) { return frcp(1.f + __expf(-x)); }
__device__ __forceinline__ float ftanh(float x) {
    return 1.f - 2.f * frcp(__expf(2.f * x) + 1.f);
}
__device__ __forceinline__ void bar128() {
    asm volatile("bar.sync 1, 128;" ::: "memory");
}
__device__ __forceinline__ void ldsm_x4(uint32_t* r, uint32_t addr) {
    asm volatile("ldmatrix.sync.aligned.m8n8.x4.shared.b16 {%0,%1,%2,%3}, [%4];"
                 : "=r"(r[0]), "=r"(r[1]), "=r"(r[2]), "=r"(r[3]) : "r"(addr));
}
__device__ __forceinline__ void mma16816(float* d, const uint32_t* a, const uint32_t* b) {
    asm volatile(
        "mma.sync.aligned.m16n8k16.row.col.f32.f16.f16.f32 "
        "{%0,%1,%2,%3},{%4,%5,%6,%7},{%8,%9},{%0,%1,%2,%3};"
        : "+f"(d[0]), "+f"(d[1]), "+f"(d[2]), "+f"(d[3])
        : "r"(a[0]), "r"(a[1]), "r"(a[2]), "r"(a[3]), "r"(b[0]), "r"(b[1]));
}
__device__ __forceinline__ uint32_t smem_u32(const void* p) {
    uint32_t a;
    asm("{ .reg .u64 t; cvta.to.shared.u64 t, %1; cvt.u32.u64 %0, t; }"
        : "=r"(a) : "l"(p));
    return a;
}
// g_hh row R -> original (b,s) C row:  b = (R>>4)&15, s = (R>>8)*16 + (R&15)
__device__ __forceinline__ int crow(int R) {
    return (((R >> 4) & 15) << 8) + ((R >> 8) << 4) + (R & 15);
}

// ---------------------------------------------------------------------------
// Prep kernel: blocks [0,2000) convert w_out fp32->fp16;
// blocks [2000, 2128) do embedding + input projection (+ flag reset).
// ---------------------------------------------------------------------------
__global__ __launch_bounds__(256) void prep_kernel(
    const float* __restrict__ W,
    const int* __restrict__ tokens, const float* __restrict__ emb,
    const float* __restrict__ w_ih, const float* __restrict__ b_ih)
{
    const int tid = threadIdx.x;

    if (blockIdx.x < WCONV_BLOCKS) {
        size_t i = (size_t)blockIdx.x * 256 + tid;
        float4 v = reinterpret_cast<const float4*>(W)[i];
        __half2* d = reinterpret_cast<__half2*>(g_wh + i * 4);
        d[0] = __floats2half2_rn(v.x, v.y);
        d[1] = __floats2half2_rn(v.z, v.w);
        return;
    }

    __shared__ __align__(16) float xs[32][EMB];
    __shared__ int toks[32];

    const int g = tid;
    const int rowbase = (blockIdx.x - WCONV_BLOCKS) * 32;

    if (blockIdx.x == WCONV_BLOCKS && g < NCHUNK) g_cnt[g] = 0;
    if (g < 32) toks[g] = tokens[rowbase + g];

    float4 w4[16];
    float bi = 0.f;
    if (g < G3) {
        const float4* wr = reinterpret_cast<const float4*>(w_ih + g * EMB);
#pragma unroll
        for (int i = 0; i < 16; ++i) w4[i] = wr[i];
        bi = b_ih[g];
    }
    __syncthreads();
    for (int idx = g; idx < 32 * EMB; idx += 256) {
        int r = idx >> 6, c = idx & 63;
        xs[r][c] = emb[(int64_t)toks[r] * EMB + c];
    }
    __syncthreads();

    if (g < G3) {
#pragma unroll 4
        for (int r = 0; r < 32; ++r) {
            const float4* xv = reinterpret_cast<const float4*>(xs[r]);
            float a0 = bi, a1 = 0.f, a2 = 0.f, a3 = 0.f;
#pragma unroll
            for (int i = 0; i < 16; ++i) {
                float4 h4 = xv[i];
                a0 += w4[i].x * h4.x;
                a1 += w4[i].y * h4.y;
                a2 += w4[i].z * h4.z;
                a3 += w4[i].w * h4.w;
            }
            g_xp[(rowbase + r) * G3 + g] = (a0 + a1) + (a2 + a3);
        }
    }
}

// ---------------------------------------------------------------------------
// Fat kernel, grid = 148 (one block per SM):
//   blocks 0..15   : GRU, one batch each (128 active threads) -- exclusive SM
//   blocks 16..147 : persistent GEMM, strided over 8000 tiles, gated on flags
// ---------------------------------------------------------------------------
#define GM 128
#define GN 128
#define LDS_H 72          // halves per smem A/B row (64 + 8 pad)
#define NTILE ((VOCAB / GN) * (ROWS / GM))   // 8000
#define TPB   (VOCAB / GN)                   // tiles per by = 250

__global__ __launch_bounds__(256, 1) void fat_kernel(
    const float* __restrict__ w_hh, const float* __restrict__ b_hh,
    const float* __restrict__ bias, float* __restrict__ C)
{
    __shared__ __align__(16) char smraw[GM * LDS_H * 2 + GN * LDS_H * 2]; // 36864

    const int tid = threadIdx.x;

    if (blockIdx.x < GRU_BLOCKS) {
        // ================= GRU role (R4 design, exclusive SM) =================
        if (tid >= 128) return;
        float* hsm = reinterpret_cast<float*>(smraw);    // [2][64]

        const int t    = tid;
        const int p    = t >> 1;
        const int half = t & 1;
        const int k0   = half * 32;
        const int b    = blockIdx.x;
        const int row0 = b * SEQ;

        unsigned long long wr[16], wz[16], wn[16];
        {
            const unsigned long long* Wr =
                reinterpret_cast<const unsigned long long*>(w_hh + (p      ) * HID + k0);
            const unsigned long long* Wz =
                reinterpret_cast<const unsigned long long*>(w_hh + (p +  64) * HID + k0);
            const unsigned long long* Wn =
                reinterpret_cast<const unsigned long long*>(w_hh + (p + 128) * HID + k0);
#pragma unroll
            for (int i = 0; i < 16; ++i) { wr[i] = Wr[i]; wz[i] = Wz[i]; wn[i] = Wn[i]; }
        }
        const float br = b_hh[p], bz = b_hh[p + 64], bn = b_hh[p + 128];

        if (t < 2 * HID) hsm[t] = 0.f;

        const float* xp0 = g_xp + (size_t)row0 * G3;
        float xr = xp0[p], xz = xp0[p + 64], xn = xp0[p + 128];
        float h_old = 0.f;
        bar128();

        int cur = 0;
#pragma unroll 1
        for (int s = 0; s < SEQ; ++s) {
            float xr_n = 0.f, xz_n = 0.f, xn_n = 0.f;
            if (s + 1 < SEQ) {
                const float* xpn = g_xp + (size_t)(row0 + s + 1) * G3;
                xr_n = xpn[p]; xz_n = xpn[p + 64]; xn_n = xpn[p + 128];
            }

            unsigned long long ar0 = 0, ar1 = 0, az0 = 0, az1 = 0, an0 = 0, an1 = 0;
            const unsigned long long* h2 =
                reinterpret_cast<const unsigned long long*>(hsm + cur * HID + k0);
#pragma unroll
            for (int i = 0; i < 16; i += 2) {
                unsigned long long h0 = h2[i], h1 = h2[i + 1];
                fma2(ar0, wr[i], h0); fma2(ar1, wr[i + 1], h1);
                fma2(az0, wz[i], h0); fma2(az1, wz[i + 1], h1);
                fma2(an0, wn[i], h0); fma2(an1, wn[i + 1], h1);
            }
            float dr = upsum(ar0) + upsum(ar1);
            float dz = upsum(az0) + upsum(az1);
            float dn = upsum(an0) + upsum(an1);
            dr += __shfl_xor_sync(0xffffffffu, dr, 1);
            dz += __shfl_xor_sync(0xffffffffu, dz, 1);
            dn += __shfl_xor_sync(0xffffffffu, dn, 1);

            const float r = fsigm(xr + br + dr);
            const float z = fsigm(xz + bz + dz);
            const float n = ftanh(xn + r * (dn + bn));
            const float hnew = n + z * (h_old - n);

            if (!half) {
                hsm[(cur ^ 1) * HID + p] = hnew;
                const int hrow = ((s >> 4) * 16 + b) * 16 + (s & 15);
                g_hh[(size_t)hrow * HID + p] = __float2half_rn(hnew);
            }
            h_old = hnew;
            bar128();
            if ((s & 15) == 15 && t == 0) {
                __threadfence();
                atomicAdd(&g_cnt[s >> 4], 1);
            }
            cur ^= 1;
            xr = xr_n; xz = xz_n; xn = xn_n;
        }
        return;
    }

    // ================= persistent GEMM role =================
    __half* As = reinterpret_cast<__half*>(smraw);
    __half* Bs = As + GM * LDS_H;

    const int wid   = tid >> 5;
    const int lane  = tid & 31;
    const int wm    = wid >> 2;     // 0..1
    const int wn    = wid & 3;      // 0..3

    const uint32_t As_u = smem_u32(As);
    const uint32_t Bs_u = smem_u32(Bs);
    const int a_row = wm * 64 + ((lane >> 3) & 1) * 8 + (lane & 7);
    const int a_kc  = (lane >> 4) * 16;
    const int b_row = wn * 32 + (lane >> 4) * 8 + (lane & 7);
    const int b_kc  = ((lane >> 3) & 1) * 16;
    const int col_w = wn * 32 + 2 * (lane & 3);   // in-tile column

    uint4 apf[4], bpf[4];
    float2 bv[4];

    int tile = blockIdx.x - GRU_BLOCKS;          // 0..131

    // wait + prefetch first tile
    {
        const int by = tile / TPB, bx = tile % TPB;
        volatile int* cp = &g_cnt[by >> 1];
        while (*cp < BATCH) __nanosleep(256);
        __threadfence();
        const uint4* Ag = reinterpret_cast<const uint4*>(g_hh + (size_t)by * GM * HID);
        const uint4* Bg = reinterpret_cast<const uint4*>(g_wh + (size_t)bx * GN * HID);
#pragma unroll
        for (int i = 0; i < 4; ++i) { apf[i] = Ag[tid + i * 256]; bpf[i] = Bg[tid + i * 256]; }
#pragma unroll
        for (int nt = 0; nt < 4; ++nt)
            bv[nt] = *reinterpret_cast<const float2*>(bias + bx * GN + col_w + nt * 8);
    }

#pragma unroll 1
    for (; tile < NTILE; tile += NGEMM) {
        const int by = tile / TPB, bx = tile % TPB;
        const int nbase = bx * GN;

        // ---- STS staged tile ----
#pragma unroll
        for (int i = 0; i < 4; ++i) {
            int idx = tid + i * 256;
            int m = idx >> 3, c = idx & 7;
            *reinterpret_cast<uint4*>(As + m * LDS_H + c * 8) = apf[i];
            *reinterpret_cast<uint4*>(Bs + m * LDS_H + c * 8) = bpf[i];
        }
        __syncthreads();

        // ---- mainloop ----
        float acc[4][4][4];
#pragma unroll
        for (int mt = 0; mt < 4; ++mt)
#pragma unroll
            for (int nt = 0; nt < 4; ++nt)
#pragma unroll
                for (int r = 0; r < 4; ++r) acc[mt][nt][r] = 0.f;

#pragma unroll
        for (int ks = 0; ks < 4; ++ks) {
            uint32_t a[4][4], bfr[2][4];
#pragma unroll
            for (int mt = 0; mt < 4; ++mt)
                ldsm_x4(a[mt], As_u + (uint32_t)((a_row + mt * 16) * 144 + ks * 32 + a_kc));
#pragma unroll
            for (int p = 0; p < 2; ++p)
                ldsm_x4(bfr[p], Bs_u + (uint32_t)((b_row + p * 16) * 144 + ks * 32 + b_kc));
#pragma unroll
            for (int mt = 0; mt < 4; ++mt)
#pragma unroll
                for (int nt = 0; nt < 4; ++nt)
                    mma16816(acc[mt][nt], a[mt], &bfr[nt >> 1][(nt & 1) * 2]);
        }
        __syncthreads();   // all ldsm done -> next STS safe after this point

        // hold this tile's bias before prefetch overwrites
        const float2 bv0 = bv[0], bv1 = bv[1], bv2 = bv[2], bv3 = bv[3];

        // ---- prefetch next tile (overlaps epilogue) ----
        const int t2 = tile + NGEMM;
        if (t2 < NTILE) {
            const int by2 = t2 / TPB, bx2 = t2 % TPB;
            volatile int* cp = &g_cnt[by2 >> 1];
            while (*cp < BATCH) __nanosleep(256);
            __threadfence();
            const uint4* Ag = reinterpret_cast<const uint4*>(g_hh + (size_t)by2 * GM * HID);
            const uint4* Bg = reinterpret_cast<const uint4*>(g_wh + (size_t)bx2 * GN * HID);
#pragma unroll
            for (int i = 0; i < 4; ++i) { apf[i] = Ag[tid + i * 256]; bpf[i] = Bg[tid + i * 256]; }
#pragma unroll
            for (int nt = 0; nt < 4; ++nt)
                bv[nt] = *reinterpret_cast<const float2*>(bias + bx2 * GN + col_w + nt * 8);
        }

        // ---- epilogue: bias add + direct float2 stores (row-permuted C) ----
        const int col_l = nbase + col_w;
        const int Rbase = by * GM + wm * 64 + (lane >> 2);
        const float2 bvv[4] = { bv0, bv1, bv2, bv3 };
#pragma unroll
        for (int mt = 0; mt < 4; ++mt) {
            const size_t r0 = (size_t)crow(Rbase + mt * 16)     * VOCAB;
            const size_t r1 = (size_t)crow(Rbase + mt * 16 + 8) * VOCAB;
#pragma unroll
            for (int nt = 0; nt < 4; ++nt) {
                float2 v0 = make_float2(acc[mt][nt][0] + bvv[nt].x,
                                        acc[mt][nt][1] + bvv[nt].y);
                float2 v1 = make_float2(acc[mt][nt][2] + bvv[nt].x,
                                        acc[mt][nt][3] + bvv[nt].y);
                *reinterpret_cast<float2*>(C + r0 + col_l + nt * 8) = v0;
                *reinterpret_cast<float2*>(C + r1 + col_l + nt * 8) = v1;
            }
        }
    }
}

// ---------------------------------------------------------------------------
// Launch
// Inputs: 0 tokens(int32) 1 emb 2 w_ih 3 w_hh 4 b_ih 5 b_hh 6 w_out 7 b_out
// ---------------------------------------------------------------------------
extern "C" void kernel_launch(void* const* d_in, const int* in_sizes, int n_in,
                              void* d_out, int out_size)
{
    const int*   tokens = (const int*)  d_in[0];
    const float* emb    = (const float*)d_in[1];
    const float* w_ih   = (const float*)d_in[2];
    const float* w_hh   = (const float*)d_in[3];
    const float* b_ih   = (const float*)d_in[4];
    const float* b_hh   = (const float*)d_in[5];
    const float* w_out  = (const float*)d_in[6];
    const float* b_out  = (const float*)d_in[7];
    float* out = (float*)d_out;

    (void)in_sizes; (void)n_in; (void)out_size;

    prep_kernel<<<WCONV_BLOCKS + ROWS / 32, 256>>>(w_out, tokens, emb, w_ih, b_ih);
    fat_kernel<<<GRID_FAT, 256>>>(w_hh, b_hh, b_out, out);
}

// round 8
// speedup vs baseline: 1.4874x; 1.1097x over previous
#include <cuda_runtime.h>
#include <cuda_fp16.h>
#include <cstdint>

// Problem constants
#define VOCAB 32000
#define EMB   64
#define HID   64
#define BATCH 16
#define SEQ   256
#define ROWS  (BATCH*SEQ)   // 4096
#define G3    (3*HID)       // 192
#define NCHUNK 16           // 16 chunks of 16 steps
#define GRU_BLOCKS 16
#define NGEMM 132           // persistent GEMM blocks
#define GRID_FAT (GRU_BLOCKS + NGEMM)   // 148 = one block per SM
#define WCONV_BLOCKS 2000   // 512000 float4 / 256

// Scratch (device globals; no allocation allowed)
__device__ float  g_xp[ROWS * G3];          // x @ w_ih^T + b_ih
__device__ __half g_hh[ROWS * HID];         // h, layout [chunk][batch][s%16][64]
__device__ __half g_wh[VOCAB * HID];        // w_out fp16
__device__ int    g_cnt[NCHUNK];            // chunk completion counters

// ---------------------------------------------------------------------------
// helpers
// ---------------------------------------------------------------------------
__device__ __forceinline__ void fma2(unsigned long long& d,
                                     unsigned long long a, unsigned long long b) {
    asm("fma.rn.f32x2 %0, %1, %2, %0;" : "+l"(d) : "l"(a), "l"(b));
}
__device__ __forceinline__ float upsum(unsigned long long v) {
    unsigned lo, hi;
    asm("mov.b64 {%0,%1}, %2;" : "=r"(lo), "=r"(hi) : "l"(v));
    return __uint_as_float(lo) + __uint_as_float(hi);
}
__device__ __forceinline__ float frcp(float x) {
    float r; asm("rcp.approx.f32 %0, %1;" : "=f"(r) : "f"(x)); return r;
}
__device__ __forceinline__ float fsigm(float x) { return frcp(1.f + __expf(-x)); }
__device__ __forceinline__ float ftanh(float x) {
    return 1.f - 2.f * frcp(__expf(2.f * x) + 1.f);
}
__device__ __forceinline__ void bar128() {
    asm volatile("bar.sync 1, 128;" ::: "memory");
}
__device__ __forceinline__ void ldsm_x4(uint32_t* r, uint32_t addr) {
    asm volatile("ldmatrix.sync.aligned.m8n8.x4.shared.b16 {%0,%1,%2,%3}, [%4];"
                 : "=r"(r[0]), "=r"(r[1]), "=r"(r[2]), "=r"(r[3]) : "r"(addr));
}
__device__ __forceinline__ void mma16816(float* d, const uint32_t* a, const uint32_t* b) {
    asm volatile(
        "mma.sync.aligned.m16n8k16.row.col.f32.f16.f16.f32 "
        "{%0,%1,%2,%3},{%4,%5,%6,%7},{%8,%9},{%0,%1,%2,%3};"
        : "+f"(d[0]), "+f"(d[1]), "+f"(d[2]), "+f"(d[3])
        : "r"(a[0]), "r"(a[1]), "r"(a[2]), "r"(a[3]), "r"(b[0]), "r"(b[1]));
}
__device__ __forceinline__ uint32_t smem_u32(const void* p) {
    uint32_t a;
    asm("{ .reg .u64 t; cvta.to.shared.u64 t, %1; cvt.u32.u64 %0, t; }"
        : "=r"(a) : "l"(p));
    return a;
}
// g_hh row R -> original (b,s) C row:  b = (R>>4)&15, s = (R>>8)*16 + (R&15)
__device__ __forceinline__ int crow(int R) {
    return (((R >> 4) & 15) << 8) + ((R >> 8) << 4) + (R & 15);
}

// ---------------------------------------------------------------------------
// Prep kernel: blocks [0,2000) convert w_out fp32->fp16;
// blocks [2000, 2128) do embedding + input projection (+ flag reset).
// ---------------------------------------------------------------------------
__global__ __launch_bounds__(256) void prep_kernel(
    const float* __restrict__ W,
    const int* __restrict__ tokens, const float* __restrict__ emb,
    const float* __restrict__ w_ih, const float* __restrict__ b_ih)
{
    const int tid = threadIdx.x;

    if (blockIdx.x < WCONV_BLOCKS) {
        size_t i = (size_t)blockIdx.x * 256 + tid;
        float4 v = reinterpret_cast<const float4*>(W)[i];
        __half2* d = reinterpret_cast<__half2*>(g_wh + i * 4);
        d[0] = __floats2half2_rn(v.x, v.y);
        d[1] = __floats2half2_rn(v.z, v.w);
        return;
    }

    __shared__ __align__(16) float xs[32][EMB];
    __shared__ int toks[32];

    const int g = tid;
    const int rowbase = (blockIdx.x - WCONV_BLOCKS) * 32;

    if (blockIdx.x == WCONV_BLOCKS && g < NCHUNK) g_cnt[g] = 0;
    if (g < 32) toks[g] = tokens[rowbase + g];

    float4 w4[16];
    float bi = 0.f;
    if (g < G3) {
        const float4* wr = reinterpret_cast<const float4*>(w_ih + g * EMB);
#pragma unroll
        for (int i = 0; i < 16; ++i) w4[i] = wr[i];
        bi = b_ih[g];
    }
    __syncthreads();
    for (int idx = g; idx < 32 * EMB; idx += 256) {
        int r = idx >> 6, c = idx & 63;
        xs[r][c] = emb[(int64_t)toks[r] * EMB + c];
    }
    __syncthreads();

    if (g < G3) {
#pragma unroll 4
        for (int r = 0; r < 32; ++r) {
            const float4* xv = reinterpret_cast<const float4*>(xs[r]);
            float a0 = bi, a1 = 0.f, a2 = 0.f, a3 = 0.f;
#pragma unroll
            for (int i = 0; i < 16; ++i) {
                float4 h4 = xv[i];
                a0 += w4[i].x * h4.x;
                a1 += w4[i].y * h4.y;
                a2 += w4[i].z * h4.z;
                a3 += w4[i].w * h4.w;
            }
            g_xp[(rowbase + r) * G3 + g] = (a0 + a1) + (a2 + a3);
        }
    }
}

// ---------------------------------------------------------------------------
// Fat kernel, grid = 148 (one block per SM):
//   blocks 0..15   : GRU, one batch each (128 active threads) -- exclusive SM
//   blocks 16..147 : persistent GEMM over 128x256 tile-pairs, gated on flags
// ---------------------------------------------------------------------------
#define GM 128
#define GNP 256                              // tile-pair width
#define LDS_H 72                             // halves per smem A/B row
#define NTILE2 ((VOCAB / GNP) * (ROWS / GM)) // 125 * 32 = 4000
#define TPB2   (VOCAB / GNP)                 // 125
#define SMEM_FAT (GM * LDS_H * 2 + GNP * LDS_H * 2)   // 18432 + 36864 = 55296

__global__ __launch_bounds__(256, 1) void fat_kernel(
    const float* __restrict__ w_hh, const float* __restrict__ b_hh,
    const float* __restrict__ bias, float* __restrict__ C)
{
    extern __shared__ __align__(16) char smraw[];

    const int tid = threadIdx.x;

    if (blockIdx.x < GRU_BLOCKS) {
        // ================= GRU role (exclusive SM) =================
        if (tid >= 128) return;
        float* hsm = reinterpret_cast<float*>(smraw);    // [2][64]

        const int t    = tid;
        const int p    = t >> 1;
        const int half = t & 1;
        const int k0   = half * 32;
        const int b    = blockIdx.x;
        const int row0 = b * SEQ;

        unsigned long long wr[16], wz[16], wn[16];
        {
            const unsigned long long* Wr =
                reinterpret_cast<const unsigned long long*>(w_hh + (p      ) * HID + k0);
            const unsigned long long* Wz =
                reinterpret_cast<const unsigned long long*>(w_hh + (p +  64) * HID + k0);
            const unsigned long long* Wn =
                reinterpret_cast<const unsigned long long*>(w_hh + (p + 128) * HID + k0);
#pragma unroll
            for (int i = 0; i < 16; ++i) { wr[i] = Wr[i]; wz[i] = Wz[i]; wn[i] = Wn[i]; }
        }
        const float br = b_hh[p], bz = b_hh[p + 64], bn = b_hh[p + 128];

        if (t < 2 * HID) hsm[t] = 0.f;

        const float* xp0 = g_xp + (size_t)row0 * G3;
        float xr = xp0[p], xz = xp0[p + 64], xn = xp0[p + 128];
        float h_old = 0.f;
        bar128();

        int cur = 0;
#pragma unroll 1
        for (int s = 0; s < SEQ; ++s) {
            float xr_n = 0.f, xz_n = 0.f, xn_n = 0.f;
            if (s + 1 < SEQ) {
                const float* xpn = g_xp + (size_t)(row0 + s + 1) * G3;
                xr_n = xpn[p]; xz_n = xpn[p + 64]; xn_n = xpn[p + 128];
            }

            unsigned long long ar0 = 0, ar1 = 0, az0 = 0, az1 = 0, an0 = 0, an1 = 0;
            const unsigned long long* h2 =
                reinterpret_cast<const unsigned long long*>(hsm + cur * HID + k0);
#pragma unroll
            for (int i = 0; i < 16; i += 2) {
                unsigned long long h0 = h2[i], h1 = h2[i + 1];
                fma2(ar0, wr[i], h0); fma2(ar1, wr[i + 1], h1);
                fma2(az0, wz[i], h0); fma2(az1, wz[i + 1], h1);
                fma2(an0, wn[i], h0); fma2(an1, wn[i + 1], h1);
            }
            float dr = upsum(ar0) + upsum(ar1);
            float dz = upsum(az0) + upsum(az1);
            float dn = upsum(an0) + upsum(an1);
            dr += __shfl_xor_sync(0xffffffffu, dr, 1);
            dz += __shfl_xor_sync(0xffffffffu, dz, 1);
            dn += __shfl_xor_sync(0xffffffffu, dn, 1);

            const float r = fsigm(xr + br + dr);
            const float z = fsigm(xz + bz + dz);
            const float n = ftanh(xn + r * (dn + bn));
            const float hnew = n + z * (h_old - n);

            if (!half) {
                hsm[(cur ^ 1) * HID + p] = hnew;
                const int hrow = ((s >> 4) * 16 + b) * 16 + (s & 15);
                g_hh[(size_t)hrow * HID + p] = __float2half_rn(hnew);
            }
            h_old = hnew;
            bar128();
            if ((s & 15) == 15 && t == 0) {
                __threadfence();
                atomicAdd(&g_cnt[s >> 4], 1);
            }
            cur ^= 1;
            xr = xr_n; xz = xz_n; xn = xn_n;
        }
        return;
    }

    // ================= persistent GEMM role (128x256 tile-pairs) ============
    __half* As = reinterpret_cast<__half*>(smraw);
    __half* Bs = As + GM * LDS_H;

    const int wid   = tid >> 5;
    const int lane  = tid & 31;
    const int wm    = wid >> 2;     // 0..1
    const int wn    = wid & 3;      // 0..3

    const uint32_t As_u = smem_u32(As);
    const uint32_t Bs_u = smem_u32(Bs);
    const int a_row = wm * 64 + ((lane >> 3) & 1) * 8 + (lane & 7);
    const int a_kc  = (lane >> 4) * 16;
    const int b_row = wn * 32 + (lane >> 4) * 8 + (lane & 7);
    const int b_kc  = ((lane >> 3) & 1) * 16;
    const int col_w = wn * 32 + 2 * (lane & 3);   // in-half column

    uint4 apf[4], bpf[8];
    float2 bv[2][4];

    int tile = blockIdx.x - GRU_BLOCKS;          // 0..131

    // wait + prefetch first tile-pair
    {
        const int by = tile / TPB2, bx = tile % TPB2;
        volatile int* cp = &g_cnt[by >> 1];
        while (*cp < BATCH) __nanosleep(256);
        __threadfence();
        const uint4* Ag = reinterpret_cast<const uint4*>(g_hh + (size_t)by * GM * HID);
        const uint4* Bg = reinterpret_cast<const uint4*>(g_wh + (size_t)bx * GNP * HID);
#pragma unroll
        for (int i = 0; i < 4; ++i) apf[i] = Ag[tid + i * 256];
#pragma unroll
        for (int i = 0; i < 8; ++i) bpf[i] = Bg[tid + i * 256];
#pragma unroll
        for (int h = 0; h < 2; ++h)
#pragma unroll
            for (int nt = 0; nt < 4; ++nt)
                bv[h][nt] = *reinterpret_cast<const float2*>(
                    bias + bx * GNP + h * 128 + col_w + nt * 8);
    }

#pragma unroll 1
    for (; tile < NTILE2; tile += NGEMM) {
        const int by = tile / TPB2, bx = tile % TPB2;
        const int nbase = bx * GNP;

        // ---- STS staged tiles ----
#pragma unroll
        for (int i = 0; i < 4; ++i) {
            int idx = tid + i * 256;
            int m = idx >> 3, c = idx & 7;
            *reinterpret_cast<uint4*>(As + m * LDS_H + c * 8) = apf[i];
        }
#pragma unroll
        for (int i = 0; i < 8; ++i) {
            int idx = tid + i * 256;
            int m = idx >> 3, c = idx & 7;
            *reinterpret_cast<uint4*>(Bs + m * LDS_H + c * 8) = bpf[i];
        }
        __syncthreads();

        // ---- mainloop ----
        float acc[4][2][4][4];
#pragma unroll
        for (int mt = 0; mt < 4; ++mt)
#pragma unroll
            for (int h = 0; h < 2; ++h)
#pragma unroll
                for (int nt = 0; nt < 4; ++nt)
#pragma unroll
                    for (int r = 0; r < 4; ++r) acc[mt][h][nt][r] = 0.f;

#pragma unroll
        for (int ks = 0; ks < 4; ++ks) {
            uint32_t a[4][4], bfr[2][2][4];
#pragma unroll
            for (int mt = 0; mt < 4; ++mt)
                ldsm_x4(a[mt], As_u + (uint32_t)((a_row + mt * 16) * 144 + ks * 32 + a_kc));
#pragma unroll
            for (int h = 0; h < 2; ++h)
#pragma unroll
                for (int p = 0; p < 2; ++p)
                    ldsm_x4(bfr[h][p], Bs_u +
                        (uint32_t)((b_row + h * 128 + p * 16) * 144 + ks * 32 + b_kc));
#pragma unroll
            for (int mt = 0; mt < 4; ++mt)
#pragma unroll
                for (int h = 0; h < 2; ++h)
#pragma unroll
                    for (int nt = 0; nt < 4; ++nt)
                        mma16816(acc[mt][h][nt], a[mt], &bfr[h][nt >> 1][(nt & 1) * 2]);
        }
        __syncthreads();   // ldsm done -> next STS safe

        // hold this tile-pair's bias before prefetch overwrites
        float2 bvv[2][4];
#pragma unroll
        for (int h = 0; h < 2; ++h)
#pragma unroll
            for (int nt = 0; nt < 4; ++nt) bvv[h][nt] = bv[h][nt];

        // ---- prefetch next tile-pair (overlaps epilogue) ----
        const int t2 = tile + NGEMM;
        if (t2 < NTILE2) {
            const int by2 = t2 / TPB2, bx2 = t2 % TPB2;
            volatile int* cp = &g_cnt[by2 >> 1];
            while (*cp < BATCH) __nanosleep(256);
            __threadfence();
            const uint4* Ag = reinterpret_cast<const uint4*>(g_hh + (size_t)by2 * GM * HID);
            const uint4* Bg = reinterpret_cast<const uint4*>(g_wh + (size_t)bx2 * GNP * HID);
#pragma unroll
            for (int i = 0; i < 4; ++i) apf[i] = Ag[tid + i * 256];
#pragma unroll
            for (int i = 0; i < 8; ++i) bpf[i] = Bg[tid + i * 256];
#pragma unroll
            for (int h = 0; h < 2; ++h)
#pragma unroll
                for (int nt = 0; nt < 4; ++nt)
                    bv[h][nt] = *reinterpret_cast<const float2*>(
                        bias + bx2 * GNP + h * 128 + col_w + nt * 8);
        }

        // ---- epilogue: bias add + direct float2 stores (row-permuted C) ----
        const int Rbase = by * GM + wm * 64 + (lane >> 2);
#pragma unroll
        for (int mt = 0; mt < 4; ++mt) {
            const size_t r0 = (size_t)crow(Rbase + mt * 16)     * VOCAB;
            const size_t r1 = (size_t)crow(Rbase + mt * 16 + 8) * VOCAB;
#pragma unroll
            for (int h = 0; h < 2; ++h) {
                const int col_l = nbase + h * 128 + col_w;
#pragma unroll
                for (int nt = 0; nt < 4; ++nt) {
                    float2 v0 = make_float2(acc[mt][h][nt][0] + bvv[h][nt].x,
                                            acc[mt][h][nt][1] + bvv[h][nt].y);
                    float2 v1 = make_float2(acc[mt][h][nt][2] + bvv[h][nt].x,
                                            acc[mt][h][nt][3] + bvv[h][nt].y);
                    *reinterpret_cast<float2*>(C + r0 + col_l + nt * 8) = v0;
                    *reinterpret_cast<float2*>(C + r1 + col_l + nt * 8) = v1;
                }
            }
        }
    }
}

// ---------------------------------------------------------------------------
// Launch
// Inputs: 0 tokens(int32) 1 emb 2 w_ih 3 w_hh 4 b_ih 5 b_hh 6 w_out 7 b_out
// ---------------------------------------------------------------------------
extern "C" void kernel_launch(void* const* d_in, const int* in_sizes, int n_in,
                              void* d_out, int out_size)
{
    const int*   tokens = (const int*)  d_in[0];
    const float* emb    = (const float*)d_in[1];
    const float* w_ih   = (const float*)d_in[2];
    const float* w_hh   = (const float*)d_in[3];
    const float* b_ih   = (const float*)d_in[4];
    const float* b_hh   = (const float*)d_in[5];
    const float* w_out  = (const float*)d_in[6];
    const float* b_out  = (const float*)d_in[7];
    float* out = (float*)d_out;

    (void)in_sizes; (void)n_in; (void)out_size;

    cudaFuncSetAttribute(fat_kernel,
                         cudaFuncAttributeMaxDynamicSharedMemorySize, SMEM_FAT);

    prep_kernel<<<WCONV_BLOCKS + ROWS / 32, 256>>>(w_out, tokens, emb, w_ih, b_ih);
    fat_kernel<<<GRID_FAT, 256, SMEM_FAT>>>(w_hh, b_hh, b_out, out);
}

// round 9
// speedup vs baseline: 1.4917x; 1.0029x over previous
#include <cuda_runtime.h>
#include <cuda_fp16.h>
#include <cstdint>

// Problem constants
#define VOCAB 32000
#define EMB   64
#define HID   64
#define BATCH 16
#define SEQ   256
#define ROWS  (BATCH*SEQ)   // 4096
#define G3    (3*HID)       // 192
#define NCHUNK 16           // 16 chunks of 16 steps
#define GRU_BLOCKS 16
#define NGEMM_BLK 132
#define NWORK (NGEMM_BLK * 2)            // 264 GEMM workers
#define GRID_FAT (GRU_BLOCKS + NGEMM_BLK) // 148 = one block per SM
#define WCONV_BLOCKS 2000   // 512000 float4 / 256

// GEMM tiling
#define GM 128
#define GN 128
#define LDS_H 72                             // halves per smem row (64+8 pad)
#define TILE_SM (GM * LDS_H * 2 + GN * LDS_H * 2)  // 36864 B per half
#define SMEM_FAT (2 * TILE_SM)                      // 73728 B
#define NTILE ((VOCAB / GN) * (ROWS / GM))   // 250*32 = 8000
#define TPB   (VOCAB / GN)                   // 250

// Scratch (device globals; no allocation allowed)
__device__ float  g_xp[ROWS * G3];          // x @ w_ih^T + b_ih
__device__ __half g_hh[ROWS * HID];         // h, layout [chunk][batch][s%16][64]
__device__ __half g_wh[VOCAB * HID];        // w_out fp16
__device__ int    g_cnt[NCHUNK];            // chunk completion counters

// ---------------------------------------------------------------------------
// helpers
// ---------------------------------------------------------------------------
__device__ __forceinline__ void fma2(unsigned long long& d,
                                     unsigned long long a, unsigned long long b) {
    asm("fma.rn.f32x2 %0, %1, %2, %0;" : "+l"(d) : "l"(a), "l"(b));
}
__device__ __forceinline__ float upsum(unsigned long long v) {
    unsigned lo, hi;
    asm("mov.b64 {%0,%1}, %2;" : "=r"(lo), "=r"(hi) : "l"(v));
    return __uint_as_float(lo) + __uint_as_float(hi);
}
__device__ __forceinline__ float frcp(float x) {
    float r; asm("rcp.approx.f32 %0, %1;" : "=f"(r) : "f"(x)); return r;
}
__device__ __forceinline__ float fsigm(float x) { return frcp(1.f + __expf(-x)); }
__device__ __forceinline__ float ftanh(float x) {
    return 1.f - 2.f * frcp(__expf(2.f * x) + 1.f);
}
__device__ __forceinline__ void bar_named(int id, int nthreads) {
    asm volatile("bar.sync %0, %1;" :: "r"(id), "r"(nthreads) : "memory");
}
__device__ __forceinline__ void ldsm_x4(uint32_t* r, uint32_t addr) {
    asm volatile("ldmatrix.sync.aligned.m8n8.x4.shared.b16 {%0,%1,%2,%3}, [%4];"
                 : "=r"(r[0]), "=r"(r[1]), "=r"(r[2]), "=r"(r[3]) : "r"(addr));
}
__device__ __forceinline__ void mma16816(float* d, const uint32_t* a, const uint32_t* b) {
    asm volatile(
        "mma.sync.aligned.m16n8k16.row.col.f32.f16.f16.f32 "
        "{%0,%1,%2,%3},{%4,%5,%6,%7},{%8,%9},{%0,%1,%2,%3};"
        : "+f"(d[0]), "+f"(d[1]), "+f"(d[2]), "+f"(d[3])
        : "r"(a[0]), "r"(a[1]), "r"(a[2]), "r"(a[3]), "r"(b[0]), "r"(b[1]));
}
__device__ __forceinline__ uint32_t smem_u32(const void* p) {
    uint32_t a;
    asm("{ .reg .u64 t; cvta.to.shared.u64 t, %1; cvt.u32.u64 %0, t; }"
        : "=r"(a) : "l"(p));
    return a;
}
// g_hh row R -> original (b,s) C row:  b = (R>>4)&15, s = (R>>8)*16 + (R&15)
__device__ __forceinline__ int crow(int R) {
    return (((R >> 4) & 15) << 8) + ((R >> 8) << 4) + (R & 15);
}

// ---------------------------------------------------------------------------
// Prep kernel: blocks [0,2000) convert w_out fp32->fp16;
// blocks [2000, 2128) do embedding + input projection (+ flag reset).
// ---------------------------------------------------------------------------
__global__ __launch_bounds__(256) void prep_kernel(
    const float* __restrict__ W,
    const int* __restrict__ tokens, const float* __restrict__ emb,
    const float* __restrict__ w_ih, const float* __restrict__ b_ih)
{
    const int tid = threadIdx.x;

    if (blockIdx.x < WCONV_BLOCKS) {
        size_t i = (size_t)blockIdx.x * 256 + tid;
        float4 v = reinterpret_cast<const float4*>(W)[i];
        __half2* d = reinterpret_cast<__half2*>(g_wh + i * 4);
        d[0] = __floats2half2_rn(v.x, v.y);
        d[1] = __floats2half2_rn(v.z, v.w);
        return;
    }

    __shared__ __align__(16) float xs[32][EMB];
    __shared__ int toks[32];

    const int g = tid;
    const int rowbase = (blockIdx.x - WCONV_BLOCKS) * 32;

    if (blockIdx.x == WCONV_BLOCKS && g < NCHUNK) g_cnt[g] = 0;
    if (g < 32) toks[g] = tokens[rowbase + g];

    float4 w4[16];
    float bi = 0.f;
    if (g < G3) {
        const float4* wr = reinterpret_cast<const float4*>(w_ih + g * EMB);
#pragma unroll
        for (int i = 0; i < 16; ++i) w4[i] = wr[i];
        bi = b_ih[g];
    }
    __syncthreads();
    for (int idx = g; idx < 32 * EMB; idx += 256) {
        int r = idx >> 6, c = idx & 63;
        xs[r][c] = emb[(int64_t)toks[r] * EMB + c];
    }
    __syncthreads();

    if (g < G3) {
#pragma unroll 4
        for (int r = 0; r < 32; ++r) {
            const float4* xv = reinterpret_cast<const float4*>(xs[r]);
            float a0 = bi, a1 = 0.f, a2 = 0.f, a3 = 0.f;
#pragma unroll
            for (int i = 0; i < 16; ++i) {
                float4 h4 = xv[i];
                a0 += w4[i].x * h4.x;
                a1 += w4[i].y * h4.y;
                a2 += w4[i].z * h4.z;
                a3 += w4[i].w * h4.w;
            }
            g_xp[(rowbase + r) * G3 + g] = (a0 + a1) + (a2 + a3);
        }
    }
}

// ---------------------------------------------------------------------------
// Fat kernel, 512 threads, grid = 148 (one block per SM):
//   blocks 0..15   : GRU, one batch each (128 active threads), 4-way k-split
//   blocks 16..147 : two independent 256-thread GEMM halves per block
//                    ("software occupancy 2"), each over its own tiles.
// ---------------------------------------------------------------------------
__global__ __launch_bounds__(512, 1) void fat_kernel(
    const float* __restrict__ w_hh, const float* __restrict__ b_hh,
    const float* __restrict__ bias, float* __restrict__ C)
{
    extern __shared__ __align__(16) char smraw[];

    const int tid = threadIdx.x;

    if (blockIdx.x < GRU_BLOCKS) {
        // ================= GRU role (exclusive SM, 4-way k-split) ===========
        if (tid >= 128) return;
        float* hsm = reinterpret_cast<float*>(smraw);    // [2][64]

        const int t  = tid;
        const int p  = t >> 2;        // h index 0..31? no: 0..31 -> wait
        const int q  = t & 3;         // k quarter
        const int k0 = q * 16;
        const int b  = blockIdx.x;
        const int row0 = b * SEQ;
        // p ranges 0..31 with 128 threads? 128/4 = 32 -> need p 0..63.
        // Use 256 threads? No: restructure — 128 threads, 2 h-indices per thread
        // would complicate. Instead: threads 0..255 active (8 warps), p=t>>2 0..63.
        // (handled below by using 256 threads)
        return; // placeholder, real GRU below uses 256 threads
    }
    // NOTE: control never reaches here for GRU blocks; see gru256 below.

    // ================= persistent GEMM role (two 256-thread halves) =========
    {
        const int h  = tid >> 8;          // half 0 or 1
        const int t  = tid & 255;
        char* base = smraw + h * TILE_SM;
        __half* As = reinterpret_cast<__half*>(base);
        __half* Bs = As + GM * LDS_H;

        const int wid  = t >> 5;
        const int lane = t & 31;
        const int wm   = wid >> 2;     // 0..1
        const int wn   = wid & 3;      // 0..3

        const uint32_t As_u = smem_u32(As);
        const uint32_t Bs_u = smem_u32(Bs);
        const int a_row = wm * 64 + ((lane >> 3) & 1) * 8 + (lane & 7);
        const int a_kc  = (lane >> 4) * 16;
        const int b_row = wn * 32 + (lane >> 4) * 8 + (lane & 7);
        const int b_kc  = ((lane >> 3) & 1) * 16;
        const int col_w = wn * 32 + 2 * (lane & 3);
        const int barid = 1 + h;

        int tile = (blockIdx.x - GRU_BLOCKS) * 2 + h;   // 0..263

#pragma unroll 1
        for (; tile < NTILE; tile += NWORK) {
            const int by = tile / TPB, bx = tile % TPB;
            const int nbase = bx * GN;

            // gate on producer chunk
            {
                volatile int* cp = &g_cnt[by >> 1];
                while (*cp < BATCH) __nanosleep(256);
                __threadfence();
            }

            // ---- stage A and B ----
            {
                const uint4* Ag = reinterpret_cast<const uint4*>(g_hh + (size_t)by * GM * HID);
                const uint4* Bg = reinterpret_cast<const uint4*>(g_wh + (size_t)nbase * HID);
#pragma unroll
                for (int i = 0; i < 4; ++i) {
                    int idx = t + i * 256;
                    int m = idx >> 3, c = idx & 7;
                    *reinterpret_cast<uint4*>(As + m * LDS_H + c * 8) = Ag[idx];
                    *reinterpret_cast<uint4*>(Bs + m * LDS_H + c * 8) = Bg[idx];
                }
            }
            bar_named(barid, 256);

            // ---- mainloop ----
            float acc[4][4][4];
#pragma unroll
            for (int mt = 0; mt < 4; ++mt)
#pragma unroll
                for (int nt = 0; nt < 4; ++nt)
#pragma unroll
                    for (int r = 0; r < 4; ++r) acc[mt][nt][r] = 0.f;

#pragma unroll
            for (int ks = 0; ks < 4; ++ks) {
                uint32_t a[4][4], bfr[2][4];
#pragma unroll
                for (int mt = 0; mt < 4; ++mt)
                    ldsm_x4(a[mt], As_u + (uint32_t)((a_row + mt * 16) * 144 + ks * 32 + a_kc));
#pragma unroll
                for (int p2 = 0; p2 < 2; ++p2)
                    ldsm_x4(bfr[p2], Bs_u + (uint32_t)((b_row + p2 * 16) * 144 + ks * 32 + b_kc));
#pragma unroll
                for (int mt = 0; mt < 4; ++mt)
#pragma unroll
                    for (int nt = 0; nt < 4; ++nt)
                        mma16816(acc[mt][nt], a[mt], &bfr[nt >> 1][(nt & 1) * 2]);
            }
            bar_named(barid, 256);   // ldsm complete -> next STS safe

            // ---- epilogue: bias + direct float2 stores (row-permuted C) ----
            const int col_l = nbase + col_w;
            float2 bv[4];
#pragma unroll
            for (int nt = 0; nt < 4; ++nt)
                bv[nt] = *reinterpret_cast<const float2*>(bias + col_l + nt * 8);

            const int Rbase = by * GM + wm * 64 + (lane >> 2);
#pragma unroll
            for (int mt = 0; mt < 4; ++mt) {
                const size_t r0 = (size_t)crow(Rbase + mt * 16)     * VOCAB;
                const size_t r1 = (size_t)crow(Rbase + mt * 16 + 8) * VOCAB;
#pragma unroll
                for (int nt = 0; nt < 4; ++nt) {
                    float2 v0 = make_float2(acc[mt][nt][0] + bv[nt].x,
                                            acc[mt][nt][1] + bv[nt].y);
                    float2 v1 = make_float2(acc[mt][nt][2] + bv[nt].x,
                                            acc[mt][nt][3] + bv[nt].y);
                    *reinterpret_cast<float2*>(C + r0 + col_l + nt * 8) = v0;
                    *reinterpret_cast<float2*>(C + r1 + col_l + nt * 8) = v1;
                }
            }
        }
        return;
    }
}

// ---------------------------------------------------------------------------
// GRU kernel-within-kernel: implemented as a separate branch with 256 threads.
// (Defined as its own device path inside fat_kernel2 below.)
// ---------------------------------------------------------------------------
// To keep the register budget and code simple, the GRU is its own __global__
// launched into the same grid via block index — see fat_kernel2.

__global__ __launch_bounds__(512, 1) void fat_kernel2(
    const float* __restrict__ w_hh, const float* __restrict__ b_hh,
    const float* __restrict__ bias, float* __restrict__ C)
{
    extern __shared__ __align__(16) char smraw[];
    const int tid = threadIdx.x;

    if (blockIdx.x < GRU_BLOCKS) {
        // ============ GRU role: 256 threads, 4 per h-index ============
        if (tid >= 256) return;
        float* hsm = reinterpret_cast<float*>(smraw);    // [2][64]

        const int t  = tid;
        const int p  = t >> 2;        // 0..63
        const int q  = t & 3;
        const int k0 = q * 16;
        const int b  = blockIdx.x;
        const int row0 = b * SEQ;

        unsigned long long wr[8], wz[8], wn[8];
        {
            const unsigned long long* Wr =
                reinterpret_cast<const unsigned long long*>(w_hh + (p      ) * HID + k0);
            const unsigned long long* Wz =
                reinterpret_cast<const unsigned long long*>(w_hh + (p +  64) * HID + k0);
            const unsigned long long* Wn =
                reinterpret_cast<const unsigned long long*>(w_hh + (p + 128) * HID + k0);
#pragma unroll
            for (int i = 0; i < 8; ++i) { wr[i] = Wr[i]; wz[i] = Wz[i]; wn[i] = Wn[i]; }
        }
        const float br = b_hh[p], bz = b_hh[p + 64], bn = b_hh[p + 128];

        if (t < 2 * HID) hsm[t] = 0.f;

        const float* xp0 = g_xp + (size_t)row0 * G3;
        float xr = xp0[p], xz = xp0[p + 64], xn = xp0[p + 128];
        float h_old = 0.f;
        bar_named(1, 256);

        int cur = 0;
#pragma unroll 1
        for (int s = 0; s < SEQ; ++s) {
            float xr_n = 0.f, xz_n = 0.f, xn_n = 0.f;
            if (s + 1 < SEQ) {
                const float* xpn = g_xp + (size_t)(row0 + s + 1) * G3;
                xr_n = xpn[p]; xz_n = xpn[p + 64]; xn_n = xpn[p + 128];
            }

            unsigned long long ar0 = 0, ar1 = 0, az0 = 0, az1 = 0, an0 = 0, an1 = 0;
            const unsigned long long* h2 =
                reinterpret_cast<const unsigned long long*>(hsm + cur * HID + k0);
#pragma unroll
            for (int i = 0; i < 8; i += 2) {
                unsigned long long h0 = h2[i], h1 = h2[i + 1];
                fma2(ar0, wr[i], h0); fma2(ar1, wr[i + 1], h1);
                fma2(az0, wz[i], h0); fma2(az1, wz[i + 1], h1);
                fma2(an0, wn[i], h0); fma2(an1, wn[i + 1], h1);
            }
            float dr = upsum(ar0) + upsum(ar1);
            float dz = upsum(az0) + upsum(az1);
            float dn = upsum(an0) + upsum(an1);
            dr += __shfl_xor_sync(0xffffffffu, dr, 1);
            dz += __shfl_xor_sync(0xffffffffu, dz, 1);
            dn += __shfl_xor_sync(0xffffffffu, dn, 1);
            dr += __shfl_xor_sync(0xffffffffu, dr, 2);
            dz += __shfl_xor_sync(0xffffffffu, dz, 2);
            dn += __shfl_xor_sync(0xffffffffu, dn, 2);

            const float r = fsigm(xr + br + dr);
            const float z = fsigm(xz + bz + dz);
            const float n = ftanh(xn + r * (dn + bn));
            const float hnew = n + z * (h_old - n);

            if (q == 0) {
                hsm[(cur ^ 1) * HID + p] = hnew;
                const int hrow = ((s >> 4) * 16 + b) * 16 + (s & 15);
                g_hh[(size_t)hrow * HID + p] = __float2half_rn(hnew);
            }
            h_old = hnew;
            bar_named(1, 256);
            if ((s & 15) == 15 && t == 0) {
                __threadfence();
                atomicAdd(&g_cnt[s >> 4], 1);
            }
            cur ^= 1;
            xr = xr_n; xz = xz_n; xn = xn_n;
        }
        return;
    }

    // ============ GEMM role: two independent 256-thread halves ============
    const int h  = tid >> 8;
    const int t  = tid & 255;
    char* base = smraw + h * TILE_SM;
    __half* As = reinterpret_cast<__half*>(base);
    __half* Bs = As + GM * LDS_H;

    const int wid  = t >> 5;
    const int lane = t & 31;
    const int wm   = wid >> 2;
    const int wn   = wid & 3;

    const uint32_t As_u = smem_u32(As);
    const uint32_t Bs_u = smem_u32(Bs);
    const int a_row = wm * 64 + ((lane >> 3) & 1) * 8 + (lane & 7);
    const int a_kc  = (lane >> 4) * 16;
    const int b_row = wn * 32 + (lane >> 4) * 8 + (lane & 7);
    const int b_kc  = ((lane >> 3) & 1) * 16;
    const int col_w = wn * 32 + 2 * (lane & 3);
    const int barid = 1 + h;

    int tile = (blockIdx.x - GRU_BLOCKS) * 2 + h;   // 0..263

#pragma unroll 1
    for (; tile < NTILE; tile += NWORK) {
        const int by = tile / TPB, bx = tile % TPB;
        const int nbase = bx * GN;

        {
            volatile int* cp = &g_cnt[by >> 1];
            while (*cp < BATCH) __nanosleep(256);
            __threadfence();
        }

        {
            const uint4* Ag = reinterpret_cast<const uint4*>(g_hh + (size_t)by * GM * HID);
            const uint4* Bg = reinterpret_cast<const uint4*>(g_wh + (size_t)nbase * HID);
#pragma unroll
            for (int i = 0; i < 4; ++i) {
                int idx = t + i * 256;
                int m = idx >> 3, c = idx & 7;
                *reinterpret_cast<uint4*>(As + m * LDS_H + c * 8) = Ag[idx];
                *reinterpret_cast<uint4*>(Bs + m * LDS_H + c * 8) = Bg[idx];
            }
        }
        bar_named(barid, 256);

        float acc[4][4][4];
#pragma unroll
        for (int mt = 0; mt < 4; ++mt)
#pragma unroll
            for (int nt = 0; nt < 4; ++nt)
#pragma unroll
                for (int r = 0; r < 4; ++r) acc[mt][nt][r] = 0.f;

#pragma unroll
        for (int ks = 0; ks < 4; ++ks) {
            uint32_t a[4][4], bfr[2][4];
#pragma unroll
            for (int mt = 0; mt < 4; ++mt)
                ldsm_x4(a[mt], As_u + (uint32_t)((a_row + mt * 16) * 144 + ks * 32 + a_kc));
#pragma unroll
            for (int p2 = 0; p2 < 2; ++p2)
                ldsm_x4(bfr[p2], Bs_u + (uint32_t)((b_row + p2 * 16) * 144 + ks * 32 + b_kc));
#pragma unroll
            for (int mt = 0; mt < 4; ++mt)
#pragma unroll
                for (int nt = 0; nt < 4; ++nt)
                    mma16816(acc[mt][nt], a[mt], &bfr[nt >> 1][(nt & 1) * 2]);
        }
        bar_named(barid, 256);

        const int col_l = nbase + col_w;
        float2 bv[4];
#pragma unroll
        for (int nt = 0; nt < 4; ++nt)
            bv[nt] = *reinterpret_cast<const float2*>(bias + col_l + nt * 8);

        const int Rbase = by * GM + wm * 64 + (lane >> 2);
#pragma unroll
        for (int mt = 0; mt < 4; ++mt) {
            const size_t r0 = (size_t)crow(Rbase + mt * 16)     * VOCAB;
            const size_t r1 = (size_t)crow(Rbase + mt * 16 + 8) * VOCAB;
#pragma unroll
            for (int nt = 0; nt < 4; ++nt) {
                float2 v0 = make_float2(acc[mt][nt][0] + bv[nt].x,
                                        acc[mt][nt][1] + bv[nt].y);
                float2 v1 = make_float2(acc[mt][nt][2] + bv[nt].x,
                                        acc[mt][nt][3] + bv[nt].y);
                *reinterpret_cast<float2*>(C + r0 + col_l + nt * 8) = v0;
                *reinterpret_cast<float2*>(C + r1 + col_l + nt * 8) = v1;
            }
        }
    }
}

// ---------------------------------------------------------------------------
// Launch
// Inputs: 0 tokens(int32) 1 emb 2 w_ih 3 w_hh 4 b_ih 5 b_hh 6 w_out 7 b_out
// ---------------------------------------------------------------------------
extern "C" void kernel_launch(void* const* d_in, const int* in_sizes, int n_in,
                              void* d_out, int out_size)
{
    const int*   tokens = (const int*)  d_in[0];
    const float* emb    = (const float*)d_in[1];
    const float* w_ih   = (const float*)d_in[2];
    const float* w_hh   = (const float*)d_in[3];
    const float* b_ih   = (const float*)d_in[4];
    const float* b_hh   = (const float*)d_in[5];
    const float* w_out  = (const float*)d_in[6];
    const float* b_out  = (const float*)d_in[7];
    float* out = (float*)d_out;

    (void)in_sizes; (void)n_in; (void)out_size;

    cudaFuncSetAttribute(fat_kernel2,
                         cudaFuncAttributeMaxDynamicSharedMemorySize, SMEM_FAT);

    prep_kernel<<<WCONV_BLOCKS + ROWS / 32, 256>>>(w_out, tokens, emb, w_ih, b_ih);
    fat_kernel2<<<GRID_FAT, 512, SMEM_FAT>>>(w_hh, b_hh, b_out, out);
}